// round 5
// baseline (speedup 1.0000x reference)
#include <cuda_runtime.h>
#include <cstdint>

// Problem constants
#define BATCH   32
#define HID     1024
#define NGATE   4096          // 4*HID
#define TSTEPS  511           // T-1
#define MTOT    16352         // TSTEPS*BATCH
#define RES_ELEMS (511*32*1024)

// ---------------- device scratch (no runtime allocation allowed) -------------
__device__ float    g_xp[(size_t)MTOT * NGATE];    // x-projection (+bias), fp32
__device__ unsigned g_hp[2][128 * 32 * 8];         // h double-buffered, tf32 frag-packed
__device__ unsigned g_flag[128 * 32];              // per-CTA publish counters, 128B apart

// ---------------- small helpers ----------------------------------------------
__device__ __forceinline__ unsigned f2tf(float f) {
    unsigned u;
    asm("cvt.rna.tf32.f32 %0, %1;" : "=r"(u) : "f"(f));
    return u;
}
__device__ __forceinline__ uint4 ldcg4(const unsigned* p) {
    uint4 v;
    asm volatile("ld.global.cg.v4.u32 {%0,%1,%2,%3}, [%4];"
                 : "=r"(v.x), "=r"(v.y), "=r"(v.z), "=r"(v.w) : "l"(p));
    return v;
}
__device__ __forceinline__ unsigned ldacq(const unsigned* p) {
    unsigned v;
    asm volatile("ld.acquire.gpu.global.u32 %0, [%1];" : "=r"(v) : "l"(p));
    return v;
}
__device__ __forceinline__ void strel(unsigned* p, unsigned v) {
    asm volatile("st.release.gpu.global.u32 [%0], %1;" :: "l"(p), "r"(v));
}
__device__ __forceinline__ void mma8(float c[4], unsigned a0, unsigned a1, unsigned a2,
                                     unsigned a3, unsigned b0, unsigned b1) {
    asm volatile(
        "mma.sync.aligned.m16n8k8.row.col.f32.tf32.tf32.f32 "
        "{%0,%1,%2,%3}, {%4,%5,%6,%7}, {%8,%9}, {%0,%1,%2,%3};"
        : "+f"(c[0]), "+f"(c[1]), "+f"(c[2]), "+f"(c[3])
        : "r"(a0), "r"(a1), "r"(a2), "r"(a3), "r"(b0), "r"(b1));
}
__device__ __forceinline__ float fsig(float x) {
    return __fdividef(1.f, 1.f + __expf(-x));
}
__device__ __forceinline__ float ftanh(float x) {
    return __fmaf_rn(2.f, fsig(2.f * x), -1.f);
}
// fragment-pack slot for h element (b, j)   [identical to R4 layout]
__device__ __forceinline__ int hp_index(int b, int j) {
    int kb   = j >> 3;
    int ln   = (b & 7) * 4 + (j & 3);
    int q    = b >> 3;
    int d    = (j >> 2) & 1;
    int slot = ((q >> 1) << 2) | (d << 1) | (q & 1);
    return (kb * 32 + ln) * 8 + slot;
}

// ---------------- x_proj: xp[t*32+b][g] = emb[tgt[b][t]] . W_ih[g] + bias ----
// Also resets the lstm publish flags (stream order guarantees this completes
// before lstm_kernel starts).
__global__ void __launch_bounds__(256)
xproj_kernel(const int* __restrict__ tgt, const float* __restrict__ emb,
             const float* __restrict__ W, const float* __restrict__ b_ih,
             const float* __restrict__ b_hh)
{
    __shared__ unsigned As[128][32];   // rotated: phys col4 = (c4 + (m&7)) & 7
    __shared__ unsigned Bs[128][32];

    if (blockIdx.x == 0 && blockIdx.y == 0 && threadIdx.x < 128)
        g_flag[threadIdx.x * 32] = 0u;

    const int nb = blockIdx.x, mb = blockIdx.y;
    const int tid = threadIdx.x, lane = tid & 31, wid = tid >> 5;
    const int warp_m = wid & 1, warp_n = wid >> 1;
    const int c4 = tid & 7, row0 = tid >> 3;
    const int g = lane >> 2, tg = lane & 3;

    int toks[4];
#pragma unroll
    for (int r = 0; r < 4; ++r) {
        int m  = row0 + r * 32;
        int mg = mb * 128 + m;
        int bb = mg & 31, tt = mg >> 5;
        int tok = tgt[bb * 512 + tt];
        toks[r] = (tok < 0 || tok > 31999) ? 0 : tok;
    }

    float acc[4][4][4];
#pragma unroll
    for (int mt = 0; mt < 4; ++mt)
#pragma unroll
        for (int nt = 0; nt < 4; ++nt)
#pragma unroll
            for (int i = 0; i < 4; ++i) acc[mt][nt][i] = 0.f;

    for (int kt = 0; kt < 32; ++kt) {
        const int koff = kt * 32 + c4 * 4;
#pragma unroll
        for (int r = 0; r < 4; ++r) {
            int m = row0 + r * 32;
            float4 va = *(const float4*)(emb + (size_t)toks[r] * 1024 + koff);
            unsigned* da = &As[m][((c4 + m) & 7) * 4];
            da[0] = f2tf(va.x); da[1] = f2tf(va.y); da[2] = f2tf(va.z); da[3] = f2tf(va.w);
            float4 vb = *(const float4*)(W + (size_t)(nb * 128 + m) * 1024 + koff);
            unsigned* db = &Bs[m][((c4 + m) & 7) * 4];
            db[0] = f2tf(vb.x); db[1] = f2tf(vb.y); db[2] = f2tf(vb.z); db[3] = f2tf(vb.w);
        }
        __syncthreads();
#pragma unroll
        for (int ks = 0; ks < 4; ++ks) {
            const int kb = ks * 8;
            unsigned a[4][4], bf[4][2];
#pragma unroll
            for (int mt = 0; mt < 4; ++mt) {
                int m   = warp_m * 64 + mt * 16 + g;
                int rot = 4 * (m & 7);
                a[mt][0] = As[m    ][(kb + tg     + rot) & 31];
                a[mt][1] = As[m + 8][(kb + tg     + rot) & 31];
                a[mt][2] = As[m    ][(kb + tg + 4 + rot) & 31];
                a[mt][3] = As[m + 8][(kb + tg + 4 + rot) & 31];
            }
#pragma unroll
            for (int nt = 0; nt < 4; ++nt) {
                int n   = warp_n * 32 + nt * 8 + g;
                int rot = 4 * (n & 7);
                bf[nt][0] = Bs[n][(kb + tg     + rot) & 31];
                bf[nt][1] = Bs[n][(kb + tg + 4 + rot) & 31];
            }
#pragma unroll
            for (int mt = 0; mt < 4; ++mt)
#pragma unroll
                for (int nt = 0; nt < 4; ++nt)
                    mma8(acc[mt][nt], a[mt][0], a[mt][1], a[mt][2], a[mt][3],
                         bf[nt][0], bf[nt][1]);
        }
        __syncthreads();
    }

#pragma unroll
    for (int mt = 0; mt < 4; ++mt) {
#pragma unroll
        for (int nt = 0; nt < 4; ++nt) {
            int m0 = mb * 128 + warp_m * 64 + mt * 16 + g;
            int n0 = nb * 128 + warp_n * 32 + nt * 8 + tg * 2;
            float bia0 = b_ih[n0] + b_hh[n0];
            float bia1 = b_ih[n0 + 1] + b_hh[n0 + 1];
            if (m0 < MTOT) {
                g_xp[(size_t)m0 * NGATE + n0]     = acc[mt][nt][0] + bia0;
                g_xp[(size_t)m0 * NGATE + n0 + 1] = acc[mt][nt][1] + bia1;
            }
            if (m0 + 8 < MTOT) {
                g_xp[(size_t)(m0 + 8) * NGATE + n0]     = acc[mt][nt][2] + bia0;
                g_xp[(size_t)(m0 + 8) * NGATE + n0 + 1] = acc[mt][nt][3] + bia1;
            }
        }
    }
}

// ---------------- persistent recurrent kernel --------------------------------
// 128 CTAs x 256 threads. CTA c owns hidden units [c*8, c*8+8).
// NO global barrier: per-CTA publish flags. Warp wid consumes h slice
// kb in [wid*16, wid*16+16) == exactly producers CTAs wid*16..+15, so each
// warp acquire-polls only its 16 producer flags, then runs its K-split mma.
// Publish: STG packed h -> __syncthreads -> threadfence -> flag[c] = t+2.
__global__ void __launch_bounds__(256, 1)
lstm_kernel(const float* __restrict__ h0, const float* __restrict__ c0,
            const float* __restrict__ W_hh, float* __restrict__ out, int out_size)
{
    __shared__ float red[8448];   // idx(m,n,w) = (m*33+n)*8+w

    const int tid = threadIdx.x, lane = tid & 31, wid = tid >> 5;
    const int g = lane >> 2, tg = lane & 3;
    const int j0 = blockIdx.x * 8;
    const int b = tid >> 3, jj = tid & 7;           // this thread's cell (b, j0+jj)
    const int hp_idx = hp_index(b, j0 + jj);

    // ---- load this CTA's W_hh fragments into registers (tf32) ----
    unsigned bw[16][4][2];
#pragma unroll
    for (int s = 0; s < 16; ++s) {
#pragma unroll
        for (int nt = 0; nt < 4; ++nt) {
            int r = nt * 8 + g;                 // local gate-row 0..31
            int q = r >> 3, jr = r & 7;
            const float* wrow = W_hh + (size_t)(q * 1024 + j0 + jr) * 1024
                                     + wid * 128 + s * 8 + tg;
            bw[s][nt][0] = f2tf(wrow[0]);
            bw[s][nt][1] = f2tf(wrow[4]);
        }
    }

    float c_reg = c0[b * 1024 + j0 + jj];
    float* out_cell = out + ((size_t)b * TSTEPS) * 1024 + j0 + jj;

    // ---- prologue: pack OUR OWN units' h0 slice, publish flag = 1 ----
    g_hp[0][hp_idx] = f2tf(h0[b * 1024 + j0 + jj]);
    __syncthreads();
    if (tid == 0) {
        __threadfence();
        strel(&g_flag[blockIdx.x * 32], 1u);
    }

    const unsigned* myflag = &g_flag[(wid * 16 + (lane & 15)) * 32];

    for (int t = 0; t < TSTEPS; ++t) {
        const unsigned* hb = g_hp[t & 1];

        // prefetch gate pre-activations (streaming; consumed after mma phase)
        float xpv[4];
        const float* xprow = &g_xp[(size_t)(t * 32 + b) * NGATE + j0 + jj];
#pragma unroll
        for (int q = 0; q < 4; ++q) xpv[q] = __ldcs(xprow + q * 1024);

        // wait until THIS warp's 16 producers have published h_t
        {
            const unsigned need = (unsigned)(t + 1);
            while (true) {
                unsigned v = ldacq(myflag);
                if (__all_sync(0xffffffffu, v >= need)) break;
            }
        }

        // mma phase: warp wid owns K slice [wid*128, wid*128+128)
        float C[8][4];
#pragma unroll
        for (int i = 0; i < 8; ++i) { C[i][0] = 0.f; C[i][1] = 0.f; C[i][2] = 0.f; C[i][3] = 0.f; }

#pragma unroll
        for (int s = 0; s < 16; ++s) {
            const unsigned* p = hb + ((wid * 16 + s) * 32 + lane) * 8;
            uint4 A0 = ldcg4(p);        // batches 0..15
            uint4 A1 = ldcg4(p + 4);    // batches 16..31
#pragma unroll
            for (int nt = 0; nt < 4; ++nt) {
                mma8(C[nt],     A0.x, A0.y, A0.z, A0.w, bw[s][nt][0], bw[s][nt][1]);
                mma8(C[4 + nt], A1.x, A1.y, A1.z, A1.w, bw[s][nt][0], bw[s][nt][1]);
            }
        }

        // K-split partials -> SMEM
#pragma unroll
        for (int mt = 0; mt < 2; ++mt) {
#pragma unroll
            for (int nt = 0; nt < 4; ++nt) {
                float* cc = C[mt * 4 + nt];
                int m  = mt * 16 + g;
                int n0 = nt * 8 + tg * 2;
                red[((m)     * 33 + n0    ) * 8 + wid] = cc[0];
                red[((m)     * 33 + n0 + 1) * 8 + wid] = cc[1];
                red[((m + 8) * 33 + n0    ) * 8 + wid] = cc[2];
                red[((m + 8) * 33 + n0 + 1) * 8 + wid] = cc[3];
            }
        }
        __syncthreads();   // (A) partials visible

        // gate math: one thread per (b, jj)
        float z[4];
#pragma unroll
        for (int q = 0; q < 4; ++q) {
            int r = q * 8 + jj;
            const float4* p = (const float4*)&red[(b * 33 + r) * 8];
            float4 s0 = p[0], s1 = p[1];
            z[q] = xpv[q] + (((s0.x + s0.y) + (s0.z + s0.w)) +
                             ((s1.x + s1.y) + (s1.z + s1.w)));
        }
        float iv = fsig(z[0]);
        float fv = fsig(z[1]);
        float gv = ftanh(z[2]);
        float ov = fsig(z[3]);
        c_reg = fv * c_reg + iv * gv;
        float hv = ov * ftanh(c_reg);

        __stcs(out_cell + (size_t)t * 1024, hv);   // res[b][t][j], streaming

        if (t < TSTEPS - 1) {
            g_hp[(t + 1) & 1][hp_idx] = f2tf(hv);  // publish packed h_{t+1}
            __syncthreads();   // (B) h stores done + red reuse safety
            if (tid == 0) {
                __threadfence();
                strel(&g_flag[blockIdx.x * 32], (unsigned)(t + 2));
            }
        } else {
            if (out_size >= RES_ELEMS + 2 * BATCH * HID) {
                out[RES_ELEMS + b * 1024 + j0 + jj]               = hv;     // hT
                out[RES_ELEMS + BATCH * HID + b * 1024 + j0 + jj] = c_reg;  // cT
            }
        }
    }
}

// ---------------- launch ------------------------------------------------------
extern "C" void kernel_launch(void* const* d_in, const int* in_sizes, int n_in,
                              void* d_out, int out_size)
{
    const int*   tgt  = (const int*)  d_in[0];
    const float* h0   = (const float*)d_in[1];
    const float* c0   = (const float*)d_in[2];
    // d_in[3] encoder_outputs, d_in[4] src_lengths: unused by the reference
    const float* emb  = (const float*)d_in[5];
    const float* W_ih = (const float*)d_in[6];
    const float* W_hh = (const float*)d_in[7];
    const float* b_ih = (const float*)d_in[8];
    const float* b_hh = (const float*)d_in[9];
    float* out = (float*)d_out;

    dim3 grid_x(32, 128);                 // (n blocks, m blocks)
    xproj_kernel<<<grid_x, 256>>>(tgt, emb, W_ih, b_ih, b_hh);

    lstm_kernel<<<128, 256>>>(h0, c0, W_hh, out, out_size);
}

// round 6
// speedup vs baseline: 1.3899x; 1.3899x over previous
#include <cuda_runtime.h>
#include <cuda_fp16.h>
#include <cstdint>

// Problem constants
#define BATCH   32
#define HID     1024
#define NGATE   4096          // 4*HID
#define TSTEPS  511           // T-1
#define MTOT    16352         // TSTEPS*BATCH
#define RES_ELEMS (511*32*1024)

// ---------------- device scratch (no runtime allocation allowed) -------------
__device__ float    g_xp[(size_t)MTOT * NGATE];    // x-projection (+bias), fp32
__device__ unsigned g_hp[2][64 * 32 * 8];          // h double-buffered, fp16 frag-packed (64KB each)
__device__ unsigned g_cnt1[8 * 32];                // level-1 barrier counters, 128B apart
__device__ unsigned g_cnt2;                        // level-2 counter
__device__ unsigned g_epoch;                       // released epoch (monotonic across replays)

// ---------------- small helpers ----------------------------------------------
__device__ __forceinline__ unsigned f2tf(float f) {
    unsigned u;
    asm("cvt.rna.tf32.f32 %0, %1;" : "=r"(u) : "f"(f));
    return u;
}
__device__ __forceinline__ uint4 ldcg4(const unsigned* p) {
    uint4 v;
    asm volatile("ld.global.cg.v4.u32 {%0,%1,%2,%3}, [%4];"
                 : "=r"(v.x), "=r"(v.y), "=r"(v.z), "=r"(v.w) : "l"(p));
    return v;
}
__device__ __forceinline__ unsigned ldacq(const unsigned* p) {
    unsigned v;
    asm volatile("ld.acquire.gpu.global.u32 %0, [%1];" : "=r"(v) : "l"(p));
    return v;
}
// tf32 mma (xproj)
__device__ __forceinline__ void mma8(float c[4], unsigned a0, unsigned a1, unsigned a2,
                                     unsigned a3, unsigned b0, unsigned b1) {
    asm volatile(
        "mma.sync.aligned.m16n8k8.row.col.f32.tf32.tf32.f32 "
        "{%0,%1,%2,%3}, {%4,%5,%6,%7}, {%8,%9}, {%0,%1,%2,%3};"
        : "+f"(c[0]), "+f"(c[1]), "+f"(c[2]), "+f"(c[3])
        : "r"(a0), "r"(a1), "r"(a2), "r"(a3), "r"(b0), "r"(b1));
}
// fp16 mma (recurrence)
__device__ __forceinline__ void mma16(float c[4], unsigned a0, unsigned a1, unsigned a2,
                                      unsigned a3, unsigned b0, unsigned b1) {
    asm volatile(
        "mma.sync.aligned.m16n8k16.row.col.f32.f16.f16.f32 "
        "{%0,%1,%2,%3}, {%4,%5,%6,%7}, {%8,%9}, {%0,%1,%2,%3};"
        : "+f"(c[0]), "+f"(c[1]), "+f"(c[2]), "+f"(c[3])
        : "r"(a0), "r"(a1), "r"(a2), "r"(a3), "r"(b0), "r"(b1));
}
__device__ __forceinline__ float fsig(float x) {
    return __fdividef(1.f, 1.f + __expf(-x));
}
__device__ __forceinline__ float ftanh(float x) {
    return __fmaf_rn(2.f, fsig(2.f * x), -1.f);
}
// fp16 fragment-pack u32-slot index for h element (b, k); (k&1) selects the half.
__device__ __forceinline__ int hp16_index(int b, int k) {
    int kb   = k >> 4;
    int d    = (k >> 3) & 1;
    int tg   = (k >> 1) & 3;
    int g    = b & 7;
    int q    = b >> 3;
    int slot = ((q >> 1) << 2) | (d << 1) | (q & 1);
    int ln   = g * 4 + tg;
    return (kb * 32 + ln) * 8 + slot;
}

// ---------------- x_proj: xp[t*32+b][g] = emb[tgt[b][t]] . W_ih[g] + bias ----
__global__ void __launch_bounds__(256)
xproj_kernel(const int* __restrict__ tgt, const float* __restrict__ emb,
             const float* __restrict__ W, const float* __restrict__ b_ih,
             const float* __restrict__ b_hh)
{
    __shared__ unsigned As[128][32];   // rotated: phys col4 = (c4 + (m&7)) & 7
    __shared__ unsigned Bs[128][32];

    const int nb = blockIdx.x, mb = blockIdx.y;
    const int tid = threadIdx.x, lane = tid & 31, wid = tid >> 5;
    const int warp_m = wid & 1, warp_n = wid >> 1;
    const int c4 = tid & 7, row0 = tid >> 3;
    const int g = lane >> 2, tg = lane & 3;

    int toks[4];
#pragma unroll
    for (int r = 0; r < 4; ++r) {
        int m  = row0 + r * 32;
        int mg = mb * 128 + m;
        int bb = mg & 31, tt = mg >> 5;
        int tok = tgt[bb * 512 + tt];
        toks[r] = (tok < 0 || tok > 31999) ? 0 : tok;
    }

    float acc[4][4][4];
#pragma unroll
    for (int mt = 0; mt < 4; ++mt)
#pragma unroll
        for (int nt = 0; nt < 4; ++nt)
#pragma unroll
            for (int i = 0; i < 4; ++i) acc[mt][nt][i] = 0.f;

    for (int kt = 0; kt < 32; ++kt) {
        const int koff = kt * 32 + c4 * 4;
#pragma unroll
        for (int r = 0; r < 4; ++r) {
            int m = row0 + r * 32;
            float4 va = *(const float4*)(emb + (size_t)toks[r] * 1024 + koff);
            unsigned* da = &As[m][((c4 + m) & 7) * 4];
            da[0] = f2tf(va.x); da[1] = f2tf(va.y); da[2] = f2tf(va.z); da[3] = f2tf(va.w);
            float4 vb = *(const float4*)(W + (size_t)(nb * 128 + m) * 1024 + koff);
            unsigned* db = &Bs[m][((c4 + m) & 7) * 4];
            db[0] = f2tf(vb.x); db[1] = f2tf(vb.y); db[2] = f2tf(vb.z); db[3] = f2tf(vb.w);
        }
        __syncthreads();
#pragma unroll
        for (int ks = 0; ks < 4; ++ks) {
            const int kb = ks * 8;
            unsigned a[4][4], bf[4][2];
#pragma unroll
            for (int mt = 0; mt < 4; ++mt) {
                int m   = warp_m * 64 + mt * 16 + g;
                int rot = 4 * (m & 7);
                a[mt][0] = As[m    ][(kb + tg     + rot) & 31];
                a[mt][1] = As[m + 8][(kb + tg     + rot) & 31];
                a[mt][2] = As[m    ][(kb + tg + 4 + rot) & 31];
                a[mt][3] = As[m + 8][(kb + tg + 4 + rot) & 31];
            }
#pragma unroll
            for (int nt = 0; nt < 4; ++nt) {
                int n   = warp_n * 32 + nt * 8 + g;
                int rot = 4 * (n & 7);
                bf[nt][0] = Bs[n][(kb + tg     + rot) & 31];
                bf[nt][1] = Bs[n][(kb + tg + 4 + rot) & 31];
            }
#pragma unroll
            for (int mt = 0; mt < 4; ++mt)
#pragma unroll
                for (int nt = 0; nt < 4; ++nt)
                    mma8(acc[mt][nt], a[mt][0], a[mt][1], a[mt][2], a[mt][3],
                         bf[nt][0], bf[nt][1]);
        }
        __syncthreads();
    }

#pragma unroll
    for (int mt = 0; mt < 4; ++mt) {
#pragma unroll
        for (int nt = 0; nt < 4; ++nt) {
            int m0 = mb * 128 + warp_m * 64 + mt * 16 + g;
            int n0 = nb * 128 + warp_n * 32 + nt * 8 + tg * 2;
            float bia0 = b_ih[n0] + b_hh[n0];
            float bia1 = b_ih[n0 + 1] + b_hh[n0 + 1];
            if (m0 < MTOT) {
                g_xp[(size_t)m0 * NGATE + n0]     = acc[mt][nt][0] + bia0;
                g_xp[(size_t)m0 * NGATE + n0 + 1] = acc[mt][nt][1] + bia1;
            }
            if (m0 + 8 < MTOT) {
                g_xp[(size_t)(m0 + 8) * NGATE + n0]     = acc[mt][nt][2] + bia0;
                g_xp[(size_t)(m0 + 8) * NGATE + n0 + 1] = acc[mt][nt][3] + bia1;
            }
        }
    }
}

// ---------------- persistent recurrent kernel --------------------------------
// 128 CTAs x 256 threads. CTA c owns hidden units [c*8, c*8+8).
// fp16 m16n8k16 mma, W_hh fragments in registers (64 u32/thread), h broadcast
// fp16 frag-packed (8MB/step through L2). Per-step sync = two-level spread-tree
// barrier: atomicAdd to cnt1[blockIdx&7] (16 CTAs each), group leaders funnel
// into cnt2, last leader bumps g_epoch; tid0 of every CTA acquire-polls epoch.
// Monotonic counters + mask tests => replay-safe without any reset.
__global__ void __launch_bounds__(256, 1)
lstm_kernel(const float* __restrict__ h0, const float* __restrict__ c0,
            const float* __restrict__ W_hh, float* __restrict__ out, int out_size)
{
    __shared__ float red[8448];   // idx(m,n,w) = (m*33+n)*8+w

    const int tid = threadIdx.x, lane = tid & 31, wid = tid >> 5;
    const int g = lane >> 2, tg = lane & 3;
    const int j0 = blockIdx.x * 8;
    const int b = tid >> 3, jj = tid & 7;           // this thread's cell (b, j0+jj)

    const unsigned e0 = g_epoch;                    // stable at kernel start (stream order)

    // ---- load this CTA's W_hh fragments into registers (fp16 pairs) ----
    // warp wid owns K slice [wid*128, wid*128+128) = k16 blocks wid*8 .. wid*8+7
    unsigned bw[8][4][2];
#pragma unroll
    for (int s = 0; s < 8; ++s) {
#pragma unroll
        for (int nt = 0; nt < 4; ++nt) {
            int r = nt * 8 + g;                 // local gate-row 0..31
            int q = r >> 3, jr = r & 7;
            const float* wrow = W_hh + (size_t)(q * 1024 + j0 + jr) * 1024
                                     + wid * 128 + s * 16;
            __half2 lo = __floats2half2_rn(wrow[2 * tg],     wrow[2 * tg + 1]);
            __half2 hi = __floats2half2_rn(wrow[8 + 2 * tg], wrow[8 + 2 * tg + 1]);
            bw[s][nt][0] = *(unsigned*)&lo;
            bw[s][nt][1] = *(unsigned*)&hi;
        }
    }

    float c_reg = c0[b * 1024 + j0 + jj];
    float* out_cell = out + ((size_t)b * TSTEPS) * 1024 + j0 + jj;

    // own h slot (u32 index + half offset)
    const int   hk      = j0 + jj;
    const int   hp_idx  = hp16_index(b, hk);
    const int   hp_half = hk & 1;

    // ---- prologue: pack own h0 slice (fp16), arrive ----
    {
        __half hv = __float2half(h0[b * 1024 + hk]);
        *(__half*)((char*)&g_hp[0][hp_idx] + hp_half * 2) = hv;
    }
    __syncthreads();
    if (tid == 0) {
        __threadfence();
        unsigned o1 = atomicAdd(&g_cnt1[(blockIdx.x & 7) * 32], 1u);
        if ((o1 & 15u) == 15u) {
            unsigned o2 = atomicAdd(&g_cnt2, 1u);
            if ((o2 & 7u) == 7u) atomicAdd(&g_epoch, 1u);
        }
    }

    for (int t = 0; t < TSTEPS; ++t) {
        const unsigned* hb = g_hp[t & 1];

        // prefetch gate pre-activations (streaming; consumed after mma phase)
        float xpv[4];
        const float* xprow = &g_xp[(size_t)(t * 32 + b) * NGATE + j0 + jj];
#pragma unroll
        for (int q = 0; q < 4; ++q) xpv[q] = __ldcs(xprow + q * 1024);

        // wait for epoch e0 + t + 1 (all CTAs published h_t)
        if (tid == 0) {
            const unsigned target = e0 + (unsigned)(t + 1);
            while ((int)(ldacq(&g_epoch) - target) < 0) { }
            __threadfence();
        }
        __syncthreads();

        // mma phase: warp wid owns k16 blocks wid*8 .. wid*8+7
        float C[8][4];
#pragma unroll
        for (int i = 0; i < 8; ++i) { C[i][0] = 0.f; C[i][1] = 0.f; C[i][2] = 0.f; C[i][3] = 0.f; }

#pragma unroll
        for (int s = 0; s < 8; ++s) {
            const unsigned* p = hb + ((wid * 8 + s) * 32 + lane) * 8;
            uint4 A0 = ldcg4(p);        // batches 0..15
            uint4 A1 = ldcg4(p + 4);    // batches 16..31
#pragma unroll
            for (int nt = 0; nt < 4; ++nt) {
                mma16(C[nt],     A0.x, A0.y, A0.z, A0.w, bw[s][nt][0], bw[s][nt][1]);
                mma16(C[4 + nt], A1.x, A1.y, A1.z, A1.w, bw[s][nt][0], bw[s][nt][1]);
            }
        }

        // K-split partials -> SMEM
#pragma unroll
        for (int mt = 0; mt < 2; ++mt) {
#pragma unroll
            for (int nt = 0; nt < 4; ++nt) {
                float* cc = C[mt * 4 + nt];
                int m  = mt * 16 + g;
                int n0 = nt * 8 + tg * 2;
                red[((m)     * 33 + n0    ) * 8 + wid] = cc[0];
                red[((m)     * 33 + n0 + 1) * 8 + wid] = cc[1];
                red[((m + 8) * 33 + n0    ) * 8 + wid] = cc[2];
                red[((m + 8) * 33 + n0 + 1) * 8 + wid] = cc[3];
            }
        }
        __syncthreads();   // partials visible

        // gate math: one thread per (b, jj)
        float z[4];
#pragma unroll
        for (int q = 0; q < 4; ++q) {
            int r = q * 8 + jj;
            const float4* p = (const float4*)&red[(b * 33 + r) * 8];
            float4 s0 = p[0], s1 = p[1];
            z[q] = xpv[q] + (((s0.x + s0.y) + (s0.z + s0.w)) +
                             ((s1.x + s1.y) + (s1.z + s1.w)));
        }
        float iv = fsig(z[0]);
        float fv = fsig(z[1]);
        float gv = ftanh(z[2]);
        float ov = fsig(z[3]);
        c_reg = fv * c_reg + iv * gv;
        float hv = ov * ftanh(c_reg);

        if (t < TSTEPS - 1) {
            // publish packed h_{t+1} FIRST (critical path), then arrive
            __half hh = __float2half(hv);
            *(__half*)((char*)&g_hp[(t + 1) & 1][hp_idx] + hp_half * 2) = hh;
            __syncthreads();   // h stores done + red reuse safety
            if (tid == 0) {
                __threadfence();
                unsigned o1 = atomicAdd(&g_cnt1[(blockIdx.x & 7) * 32], 1u);
                if ((o1 & 15u) == 15u) {
                    unsigned o2 = atomicAdd(&g_cnt2, 1u);
                    if ((o2 & 7u) == 7u) atomicAdd(&g_epoch, 1u);
                }
            }
            // streaming output store overlaps the next step's wait
            __stcs(out_cell + (size_t)t * 1024, hv);
        } else {
            __stcs(out_cell + (size_t)t * 1024, hv);
            if (out_size >= RES_ELEMS + 2 * BATCH * HID) {
                out[RES_ELEMS + b * 1024 + j0 + jj]               = hv;     // hT
                out[RES_ELEMS + BATCH * HID + b * 1024 + j0 + jj] = c_reg;  // cT
            }
        }
    }
}

// ---------------- launch ------------------------------------------------------
extern "C" void kernel_launch(void* const* d_in, const int* in_sizes, int n_in,
                              void* d_out, int out_size)
{
    const int*   tgt  = (const int*)  d_in[0];
    const float* h0   = (const float*)d_in[1];
    const float* c0   = (const float*)d_in[2];
    // d_in[3] encoder_outputs, d_in[4] src_lengths: unused by the reference
    const float* emb  = (const float*)d_in[5];
    const float* W_ih = (const float*)d_in[6];
    const float* W_hh = (const float*)d_in[7];
    const float* b_ih = (const float*)d_in[8];
    const float* b_hh = (const float*)d_in[9];
    float* out = (float*)d_out;

    dim3 grid_x(32, 128);                 // (n blocks, m blocks)
    xproj_kernel<<<grid_x, 256>>>(tgt, emb, W_ih, b_ih, b_hh);

    lstm_kernel<<<128, 256>>>(h0, c0, W_hh, out, out_size);
}